// round 1
// baseline (speedup 1.0000x reference)
#include <cuda_runtime.h>

// ImageTreensformerV6: only pyramid level 4 (global patch mean) reaches the
// output, so the whole model collapses to:
//   g[b,f]     = (1/256) * sum_{bh,bw} x[b,c,bh*16+pi,bw*16+pj],  f = c*256+pi*16+pj
//   root[b,d]  = sum_f g[b,f]*W_emb[d,f] + b_emb[d] + pos4[d]
//   logits[b,n]= sum_d root[b,d]*W_cls[n,d] + b_cls[n]

#define BATCH 64
#define CH    3
#define IMG   256
#define FDIM  768    // 3*16*16
#define DDIM  128
#define NCLS  1000

// Scratch (device globals — no allocation)
__device__ float g_gT[FDIM * BATCH];     // g transposed: [f][b], coalesced for K2
__device__ float g_root[BATCH * DDIM];   // root: [b][d]

// ---------------------------------------------------------------------------
// K1: strided grid means over x. 768 blocks = b(64) x c(3) x pg(4 pi-quarters)
// Thread t: pj4 = t&3 (covers 4 pj via float4), pi_l = (t>>2)&3, q = t>>4 = bw.
// Each thread: 16 independent LDG.128 (one per bh) -> 4 accumulators.
// Smem reduce over the 16 bw-partials -> 64 outputs per block.
// ---------------------------------------------------------------------------
__global__ __launch_bounds__(256) void k_pool(const float* __restrict__ x) {
    const int blk = blockIdx.x;
    const int pg  = blk & 3;
    const int c   = (blk >> 2) % 3;
    const int b   = blk / 12;

    const int t    = threadIdx.x;
    const int pj4  = t & 3;          // float4 column group: pj = pj4*4 .. pj4*4+3
    const int pi_l = (t >> 2) & 3;
    const int q    = t >> 4;         // bw = 0..15
    const int pi   = pg * 4 + pi_l;

    const float* base = x + ((size_t)(b * CH + c) * IMG + pi) * IMG + q * 16 + pj4 * 4;

    float a0 = 0.f, a1 = 0.f, a2 = 0.f, a3 = 0.f;
#pragma unroll
    for (int bh = 0; bh < 16; bh++) {
        float4 v = *reinterpret_cast<const float4*>(base + (size_t)bh * 16 * IMG);
        a0 += v.x; a1 += v.y; a2 += v.z; a3 += v.w;
    }

    __shared__ float4 s4[256];
    s4[(q * 4 + pi_l) * 4 + pj4] = make_float4(a0, a1, a2, a3);
    __syncthreads();

    if (t < 64) {
        const int pi_l2 = t >> 4;    // 0..3
        const int pj    = t & 15;
        const float* s = reinterpret_cast<const float*>(s4);
        float sum = 0.f;
#pragma unroll
        for (int q2 = 0; q2 < 16; q2++)
            sum += s[(q2 * 4 + pi_l2) * 16 + pj];   // conflict-free: lanes span 0..31
        const int f = c * 256 + (pg * 4 + pi_l2) * 16 + pj;
        g_gT[f * BATCH + b] = sum * (1.0f / 256.0f);
    }
}

// ---------------------------------------------------------------------------
// K2: root = g @ W_emb^T + b_emb + pos4.  16 blocks x 8 d-rows each.
// W_emb chunk staged in smem (broadcast reads); g read coalesced via g_gT.
// ---------------------------------------------------------------------------
__global__ __launch_bounds__(256) void k_emb(const float* __restrict__ W_emb,
                                             const float* __restrict__ b_emb,
                                             const float* __restrict__ pos4) {
    __shared__ float sW[8 * FDIM];   // 24 KB
    const int t  = threadIdx.x;
    const int d0 = blockIdx.x * 8;

    for (int i = t; i < 8 * FDIM; i += 256) sW[i] = W_emb[d0 * FDIM + i];
    __syncthreads();

    const int b  = t & 63;
    const int dh = t >> 6;           // 0..3 -> handles d_local dh and dh+4
    float s0 = 0.f, s1 = 0.f;
#pragma unroll 4
    for (int f = 0; f < FDIM; f++) {
        const float gv = g_gT[f * BATCH + b];   // coalesced over lanes
        s0 += gv * sW[dh * FDIM + f];           // smem broadcast
        s1 += gv * sW[(dh + 4) * FDIM + f];
    }
    const int da = d0 + dh, db = d0 + dh + 4;
    g_root[b * DDIM + da] = s0 + b_emb[da] + pos4[da];
    g_root[b * DDIM + db] = s1 + b_emb[db] + pos4[db];
}

// ---------------------------------------------------------------------------
// K3: logits = root @ W_cls^T + b_cls.  125 blocks x 8 class-rows each;
// all 64 batches per block so W_cls is read exactly once total.
// root in smem with +1 pad (stride 129) -> conflict-free lane-b reads.
// ---------------------------------------------------------------------------
__global__ __launch_bounds__(256) void k_cls(const float* __restrict__ W_cls,
                                             const float* __restrict__ b_cls,
                                             float* __restrict__ out) {
    __shared__ float sR[BATCH * 129];   // 33 KB, padded rows
    __shared__ float sW[8 * DDIM];      // 4 KB
    const int t  = threadIdx.x;
    const int n0 = blockIdx.x * 8;

    for (int i = t; i < BATCH * DDIM; i += 256) {
        const int bb = i >> 7, dd = i & 127;
        sR[bb * 129 + dd] = g_root[i];
    }
    for (int i = t; i < 8 * DDIM; i += 256) sW[i] = W_cls[n0 * DDIM + i];
    __syncthreads();

    const int b  = t & 63;
    const int nh = t >> 6;              // 0..3 -> handles n_local nh and nh+4
    float s0 = 0.f, s1 = 0.f;
#pragma unroll 8
    for (int f = 0; f < DDIM; f++) {
        const float rv = sR[b * 129 + f];   // (b+f)%32 bank -> conflict-free
        s0 += rv * sW[nh * DDIM + f];       // broadcast
        s1 += rv * sW[(nh + 4) * DDIM + f];
    }
    const int na = n0 + nh, nb = n0 + nh + 4;
    out[b * NCLS + na] = s0 + b_cls[na];
    out[b * NCLS + nb] = s1 + b_cls[nb];
}

extern "C" void kernel_launch(void* const* d_in, const int* in_sizes, int n_in,
                              void* d_out, int out_size) {
    const float* x     = (const float*)d_in[0];
    const float* W_emb = (const float*)d_in[1];
    const float* b_emb = (const float*)d_in[2];
    const float* pos4  = (const float*)d_in[7];
    const float* W_cls = (const float*)d_in[8];
    const float* b_cls = (const float*)d_in[9];
    float* out = (float*)d_out;

    k_pool<<<768, 256>>>(x);
    k_emb<<<16, 256>>>(W_emb, b_emb, pos4);
    k_cls<<<125, 256>>>(W_cls, b_cls, out);
}

// round 12
// speedup vs baseline: 2.4942x; 2.4942x over previous
#include <cuda_runtime.h>

// ImageTreensformerV6: only pyramid level 4 (global patch mean) reaches the
// output, so the whole model collapses to:
//   g[b,f]     = (1/256) * sum_{bh,bw} x[b,c,bh*16+pi,bw*16+pj],  f = c*256+pi*16+pj
//   root[b,d]  = sum_f g[b,f]*W_emb[d,f] + b_emb[d] + pos4[d]
//   logits[b,n]= sum_d root[b,d]*W_cls[n,d] + b_cls[n]

#define BATCH 64
#define CH    3
#define IMG   256
#define FDIM  768    // 3*16*16
#define DDIM  128
#define NCLS  1000

// Scratch (device globals — no allocation)
__device__ float g_gT[FDIM * BATCH];     // g transposed: [f][b], coalesced
__device__ float g_root[BATCH * DDIM];   // root: [b][d]

// ---------------------------------------------------------------------------
// K1: strided grid means over x. 768 blocks = b(64) x c(3) x pg(4 pi-quarters)
// Thread t: pj4 = t&3 (covers 4 pj via float4), pi_l = (t>>2)&3, q = t>>4 = bw.
// Each thread: 16 LDG.128, explicitly batched 8-at-a-time into a register
// array to force MLP=8 (R1 profile showed regs=31 -> ptxas could only keep
// ~4 loads in flight; launch_bounds(256,4) raises the budget to 64 regs
// while keeping 4 CTAs/SM = full occupancy).
// ---------------------------------------------------------------------------
__global__ __launch_bounds__(256, 4) void k_pool(const float* __restrict__ x) {
    const int blk = blockIdx.x;
    const int pg  = blk & 3;
    const int c   = (blk >> 2) % 3;
    const int b   = blk / 12;

    const int t    = threadIdx.x;
    const int pj4  = t & 3;          // float4 column group: pj = pj4*4 .. pj4*4+3
    const int pi_l = (t >> 2) & 3;
    const int q    = t >> 4;         // bw = 0..15
    const int pi   = pg * 4 + pi_l;

    const float* base = x + ((size_t)(b * CH + c) * IMG + pi) * IMG + q * 16 + pj4 * 4;

    float a0 = 0.f, a1 = 0.f, a2 = 0.f, a3 = 0.f;
#pragma unroll
    for (int half = 0; half < 2; half++) {
        float4 v[8];
#pragma unroll
        for (int i = 0; i < 8; i++)      // 8 independent LDG.128 in flight
            v[i] = *reinterpret_cast<const float4*>(
                base + (size_t)(half * 8 + i) * 16 * IMG);
#pragma unroll
        for (int i = 0; i < 8; i++) {
            a0 += v[i].x; a1 += v[i].y; a2 += v[i].z; a3 += v[i].w;
        }
    }

    __shared__ float4 s4[256];
    s4[(q * 4 + pi_l) * 4 + pj4] = make_float4(a0, a1, a2, a3);
    __syncthreads();

    if (t < 64) {
        const int pi_l2 = t >> 4;    // 0..3
        const int pj    = t & 15;
        const float* s = reinterpret_cast<const float*>(s4);
        float sum = 0.f;
#pragma unroll
        for (int q2 = 0; q2 < 16; q2++)
            sum += s[(q2 * 4 + pi_l2) * 16 + pj];   // conflict-free: lanes span 0..31
        const int f = c * 256 + (pg * 4 + pi_l2) * 16 + pj;
        g_gT[f * BATCH + b] = sum * (1.0f / 256.0f);
    }
}

// ---------------------------------------------------------------------------
// K2 v2: root = g @ W_emb^T + b_emb + pos4.
// 32 blocks x 4 d-rows. W chunk (4x768, 12KB) AND g streamed through smem in
// six 128x64 chunks (32KB each, contiguous -> bulk float4 coalesced loads).
// Inner loop is pure smem: lane-consecutive LDS + broadcast + FFMA.
// ---------------------------------------------------------------------------
#define FCHUNK 128
__global__ __launch_bounds__(256) void k_emb(const float* __restrict__ W_emb,
                                             const float* __restrict__ b_emb,
                                             const float* __restrict__ pos4) {
    __shared__ float sW[4 * FDIM];            // 12 KB
    __shared__ float sG[FCHUNK * BATCH];      // 32 KB
    const int t  = threadIdx.x;
    const int d0 = blockIdx.x * 4;

    for (int i = t; i < 4 * FDIM; i += 256) sW[i] = W_emb[d0 * FDIM + i];

    const int b  = t & 63;
    const int dh = t >> 6;           // 0..3
    float acc0 = 0.f, acc1 = 0.f;

    for (int ch = 0; ch < FDIM / FCHUNK; ch++) {
        // stage g chunk: contiguous region g_gT + ch*FCHUNK*64 (8192 floats)
        __syncthreads();
        const float4* src = reinterpret_cast<const float4*>(g_gT + ch * FCHUNK * BATCH);
        float4*       dst = reinterpret_cast<float4*>(sG);
#pragma unroll
        for (int i = 0; i < (FCHUNK * BATCH / 4) / 256; i++)
            dst[t + i * 256] = src[t + i * 256];
        __syncthreads();

        const float* wrow = &sW[dh * FDIM + ch * FCHUNK];
#pragma unroll 8
        for (int f = 0; f < FCHUNK; f += 2) {
            acc0 += sG[f * BATCH + b]       * wrow[f];       // lanes b: stride-1, conflict-free
            acc1 += sG[(f + 1) * BATCH + b] * wrow[f + 1];   // broadcast wrow
        }
    }
    const int d = d0 + dh;
    g_root[b * DDIM + d] = acc0 + acc1 + b_emb[d] + pos4[d];
}

// ---------------------------------------------------------------------------
// K3: logits = root @ W_cls^T + b_cls.  125 blocks x 8 class-rows each;
// all 64 batches per block so W_cls is read exactly once total.
// root in smem with +1 pad (stride 129) -> conflict-free lane-b reads.
// ---------------------------------------------------------------------------
__global__ __launch_bounds__(256) void k_cls(const float* __restrict__ W_cls,
                                             const float* __restrict__ b_cls,
                                             float* __restrict__ out) {
    __shared__ float sR[BATCH * 129];   // 33 KB, padded rows
    __shared__ float sW[8 * DDIM];      // 4 KB
    const int t  = threadIdx.x;
    const int n0 = blockIdx.x * 8;

    for (int i = t; i < BATCH * DDIM; i += 256) {
        const int bb = i >> 7, dd = i & 127;
        sR[bb * 129 + dd] = g_root[i];
    }
    for (int i = t; i < 8 * DDIM; i += 256) sW[i] = W_cls[n0 * DDIM + i];
    __syncthreads();

    const int b  = t & 63;
    const int nh = t >> 6;              // 0..3 -> handles n_local nh and nh+4
    float s0 = 0.f, s1 = 0.f;
#pragma unroll 8
    for (int f = 0; f < DDIM; f++) {
        const float rv = sR[b * 129 + f];   // (b+f)%32 bank -> conflict-free
        s0 += rv * sW[nh * DDIM + f];       // broadcast
        s1 += rv * sW[(nh + 4) * DDIM + f];
    }
    const int na = n0 + nh, nb = n0 + nh + 4;
    out[b * NCLS + na] = s0 + b_cls[na];
    out[b * NCLS + nb] = s1 + b_cls[nb];
}

extern "C" void kernel_launch(void* const* d_in, const int* in_sizes, int n_in,
                              void* d_out, int out_size) {
    const float* x     = (const float*)d_in[0];
    const float* W_emb = (const float*)d_in[1];
    const float* b_emb = (const float*)d_in[2];
    const float* pos4  = (const float*)d_in[7];
    const float* W_cls = (const float*)d_in[8];
    const float* b_cls = (const float*)d_in[9];
    float* out = (float*)d_out;

    k_pool<<<768, 256>>>(x);
    k_emb<<<32, 256>>>(W_emb, b_emb, pos4);
    k_cls<<<125, 256>>>(W_cls, b_cls, out);
}